// round 1
// baseline (speedup 1.0000x reference)
#include <cuda_runtime.h>
#include <math.h>

// Problem geometry (fixed by the reference):
//   T = 1024 time steps, C = B*D = 16*1024 = 16384 independent columns.
//   y[t][c] = x[t][c] + beta * y[t-1][c],  beta = sigmoid(beta_param)
#define T_DIM   1024
#define C_DIM   16384
#define SEG     16          // segments along T
#define L_DIM   (T_DIM/SEG) // 64 rows per segment
#define TPB     128         // threads per block = columns per block
#define NCB     (C_DIM/TPB) // 128 column-blocks
#define NBLK    (SEG*NCB)   // 2048 blocks

// Scratch in __device__ globals (no allocation allowed anywhere).
__device__ float          g_agg[SEG * C_DIM];   // per-(segment, column) aggregates: 1 MiB
__device__ volatile int   g_flag[NBLK];         // publish flags, one per block
__device__ unsigned int   g_ticket;             // scheduling-order ticket

__global__ void pli_init_kernel() {
    int i = blockIdx.x * blockDim.x + threadIdx.x;
    if (i < NBLK) g_flag[i] = 0;
    if (i == 0)  g_ticket = 0u;
}

__global__ __launch_bounds__(TPB)
void pli_scan_kernel(const float* __restrict__ x,
                     const float* __restrict__ beta_param,
                     float* __restrict__ y) {
    // --- ticket: guarantees blocks with smaller (seg) started earlier -> no deadlock
    __shared__ unsigned int s_vbid;
    if (threadIdx.x == 0) s_vbid = atomicAdd(&g_ticket, 1u);
    __syncthreads();
    const unsigned int vbid = s_vbid;
    const int seg = (int)(vbid / NCB);      // segment-major: all seg 0 first, then seg 1, ...
    const int cb  = (int)(vbid % NCB);
    const int col = cb * TPB + threadIdx.x;
    const int t0  = seg * L_DIM;

    const float bp   = beta_param[0];
    const float beta = 1.0f / (1.0f + expf(-bp));

    // --- load this segment's 64 values for my column (64 independent loads -> high MLP)
    float v[L_DIM];
    const float* xp = x + (size_t)t0 * C_DIM + col;
#pragma unroll
    for (int k = 0; k < L_DIM; ++k) v[k] = xp[(size_t)k * C_DIM];

    // --- local inclusive scan in registers
    float acc = v[0];
#pragma unroll
    for (int k = 1; k < L_DIM; ++k) { acc = fmaf(beta, acc, v[k]); v[k] = acc; }

    // --- publish aggregate (release: store, fence, syncthreads, flag)
    g_agg[seg * C_DIM + col] = acc;
    __threadfence();
    __syncthreads();
    if (threadIdx.x == 0) g_flag[vbid] = 1;

    // beta^L via repeated squaring: L = 64 = 2^6
    float betaL = beta;
#pragma unroll
    for (int i = 0; i < 6; ++i) betaL *= betaL;

    // --- decoupled lookback: P = y[t0-1] = sum_{j>=1} beta^{L*(j-1)} * agg[seg-j]
    float P = 0.0f;
    if (seg > 0) {
        float w = 1.0f;
        for (int s = seg - 1; s >= 0; --s) {
            if (threadIdx.x == 0) {
                while (g_flag[s * NCB + cb] == 0) { __nanosleep(40); }
            }
            __syncthreads();
            __threadfence();   // acquire: agg stores ordered before flag by producer
            P = fmaf(w, g_agg[s * C_DIM + col], P);
            w *= betaL;
        }
    }

    // --- final: y[t0+k] = v[k] + beta^{k+1} * P
    float* yp = y + (size_t)t0 * C_DIM + col;
    float f = beta;
#pragma unroll
    for (int k = 0; k < L_DIM; ++k) {
        yp[(size_t)k * C_DIM] = fmaf(f, P, v[k]);
        f *= beta;
    }
}

extern "C" void kernel_launch(void* const* d_in, const int* in_sizes, int n_in,
                              void* d_out, int out_size) {
    const float* x    = (const float*)d_in[0];   // x_seq [T, B, D] fp32
    const float* bp   = (const float*)d_in[1];   // beta_param scalar fp32
    float*       y    = (float*)d_out;           // [T, B, D] fp32
    (void)in_sizes; (void)n_in; (void)out_size;

    pli_init_kernel<<<(NBLK + 256) / 256, 256>>>();
    pli_scan_kernel<<<NBLK, TPB>>>(x, bp, y);
}